// round 7
// baseline (speedup 1.0000x reference)
#include <cuda_runtime.h>

#define HH 4096
#define WW 4096

// Block = 256 threads computes an 8-row x 512-col tile (16 px/thread).
// Stage rows h0-1..h0+8, cols w0-4..w0+515 in smem via coalesced float4 loads,
// then compute entirely from smem (no scalar global halo loads).

#define TROWS 10
#define TSTRIDE 520          // floats per smem row (520*4 B, 16B-aligned)

__global__ void __launch_bounds__(256) nms_kernel(
    const float* __restrict__ img,
    const float* __restrict__ theta,
    float* __restrict__ out)
{
    __shared__ float tile[TROWS][TSTRIDE];

    const int tid = threadIdx.x;
    const int bx  = blockIdx.x & 7;     // 8 tiles across
    const int by  = blockIdx.x >> 3;    // 512 tiles down
    const int w0  = bx << 9;            // tile left column (512 px wide)
    const int h0  = by << 3;            // tile top row (8 rows)

    // ---- stage phase: 10 rows x 130 float4 = 1300 vector loads ----
    #pragma unroll
    for (int i = 0; i < 6; i++) {
        int li = tid + (i << 8);
        if (li < 1300) {
            int r   = li / 130;              // smem row 0..9
            int c4  = li - r * 130;          // float4 index 0..129
            int grow = h0 - 1 + r;           // clamped rows feed only border-zeroed outputs
            grow = min(max(grow, 0), HH - 1);
            int gcol = w0 - 4 + (c4 << 2);   // clamped cols likewise unused or border-zeroed
            gcol = min(max(gcol, 0), WW - 4);
            float4 v = __ldg(reinterpret_cast<const float4*>(
                                 img + ((unsigned)grow << 12) + gcol));
            *reinterpret_cast<float4*>(&tile[r][c4 << 2]) = v;
        }
    }
    __syncthreads();

    const float RCP45 = 1.0f / 45.0f;    // RN(1/45)

    // ---- compute phase: 4 quads per thread ----
    #pragma unroll
    for (int k = 0; k < 4; k++) {
        int q  = tid + (k << 8);        // 0..1023
        int r  = q >> 7;                // tile row 0..7
        int qc = q & 127;               // quad col within tile
        int h  = h0 + r;
        int c  = w0 + (qc << 2);
        unsigned gbase = ((unsigned)h << 12) + c;

        if (h == 0 || h == HH - 1) {
            __stcs(reinterpret_cast<float4*>(out + gbase),
                   make_float4(0.f, 0.f, 0.f, 0.f));
            continue;
        }

        const float4 t4 = __ldcs(reinterpret_cast<const float4*>(theta + gbase));

        int s = (qc << 2) + 4;          // smem col of first pixel
        const float4 upv = *reinterpret_cast<const float4*>(&tile[r][s]);
        const float4 ctv = *reinterpret_cast<const float4*>(&tile[r + 1][s]);
        const float4 dnv = *reinterpret_cast<const float4*>(&tile[r + 2][s]);
        const float lup = tile[r][s - 1],     rup = tile[r][s + 4];
        const float lct = tile[r + 1][s - 1], rct = tile[r + 1][s + 4];
        const float ldn = tile[r + 2][s - 1], rdn = tile[r + 2][s + 4];

        // column j = image column (c - 1 + j)
        float row[6] = { lct, ctv.x, ctv.y, ctv.z, ctv.w, rct };
        float uu [6] = { lup, upv.x, upv.y, upv.z, upv.w, rup };
        float dn [6] = { ldn, dnv.x, dnv.y, dnv.z, dnv.w, rdn };
        float th [4] = { t4.x, t4.y, t4.z, t4.w };
        float o[4];

        #pragma unroll
        for (int i = 0; i < 4; i++) {
            // deg = theta * f32(180/pi); single +180 if negative (matches reference)
            float deg = __fmul_rn(th[i], 57.29577951308232f);
            if (deg < 0.f) deg = __fadd_rn(deg, 180.f);

            // correctly-rounded deg/45 (Markstein mul+2fma, bit-exact vs RN divide)
            float q0 = __fmul_rn(deg, RCP45);
            float rr = __fmaf_rn(-45.f, q0, deg);
            float qf = __fmaf_rn(rr, RCP45, q0);
            int   kk = __float2int_rn(qf);   // F2I.RNI = round-half-even = jnp.round

            float a, b;
            if (kk == 0 || kk == 4) { a = row[i + 2]; b = row[i];     }
            else if (kk == 1)       { a = dn [i + 2]; b = uu[i];      }
            else if (kk == 2)       { a = dn [i + 1]; b = uu[i + 1];  }
            else                    { a = dn [i];     b = uu[i + 2];  }

            float cc = row[i + 1];
            o[i] = (cc >= fmaxf(a, b)) ? cc : 0.f;
        }

        if (c == 0)       o[0] = 0.f;
        if (c == WW - 4)  o[3] = 0.f;

        __stcs(reinterpret_cast<float4*>(out + gbase),
               make_float4(o[0], o[1], o[2], o[3]));
    }
}

extern "C" void kernel_launch(void* const* d_in, const int* in_sizes, int n_in,
                              void* d_out, int out_size)
{
    const float* img   = (const float*)d_in[0];
    const float* theta = (const float*)d_in[1];
    float*       out   = (float*)d_out;

    const int grid = 8 * 512;   // 8 tiles-x * 512 tiles-y
    nms_kernel<<<grid, 256>>>(img, theta, out);
}

// round 8
// speedup vs baseline: 1.5869x; 1.5869x over previous
#include <cuda_runtime.h>

#define HH 4096
#define WW 4096
#define NPIX (HH * WW)

__global__ void __launch_bounds__(256, 7) nms_kernel(
    const float* __restrict__ img,
    const float* __restrict__ theta,
    float* __restrict__ out)
{
    unsigned idx = blockIdx.x * 256u + threadIdx.x;   // quad index
    unsigned h   = idx >> 10;            // row
    unsigned w0  = (idx & 1023u) << 2;   // quad start column
    unsigned base = (h << 12) + w0;

    if (h == 0 || h == HH - 1) {
        *reinterpret_cast<float4*>(out + base) = make_float4(0.f, 0.f, 0.f, 0.f);
        return;
    }

    const float* pc = img + base;

    // ---- 10 independent loads, front-batched (MLP=10) ----
    const float4 t4 = __ldg(reinterpret_cast<const float4*>(theta + base));
    const float4 c4 = __ldg(reinterpret_cast<const float4*>(pc));
    const float4 u4 = __ldg(reinterpret_cast<const float4*>(pc - WW));
    const float4 d4 = __ldg(reinterpret_cast<const float4*>(pc + WW));

    // corner clamps only bind for border-zeroed outputs; values never used.
    int uli = (int)base - WW - 1; if (uli < 0) uli = 0;
    int dri = (int)base + WW + 4; if (dri >= NPIX) dri = NPIX - 1;

    const float lft = __ldg(pc - 1);
    const float rgt = __ldg(pc + 4);
    const float ul  = __ldg(img + uli);
    const float ur  = __ldg(pc - WW + 4);
    const float dl  = __ldg(pc + WW - 1);
    const float dr  = __ldg(img + dri);

    const float RCP45 = 1.0f / 45.0f;   // RN(1/45)

    // column j = image column (w0 - 1 + j); named scalars, no arrays
    // up:  ul  u4.x u4.y u4.z u4.w ur
    // ct:  lft c4.x c4.y c4.z c4.w rgt
    // dn:  dl  d4.x d4.y d4.z d4.w dr
    float o[4];

    #define NMS_PX(i, UPL, UPC, UPR, CTL, CTC, CTR, DNL, DNC, DNR, TH)          \
    {                                                                            \
        float deg = __fmul_rn((TH), 57.29577951308232f);                         \
        if (deg < 0.f) deg = __fadd_rn(deg, 180.f);                              \
        float q0 = __fmul_rn(deg, RCP45);                                        \
        float rr = __fmaf_rn(-45.f, q0, deg);                                    \
        float qf = __fmaf_rn(rr, RCP45, q0);                                     \
        int   k  = __float2int_rn(qf);      /* F2I.RNI = half-even = jnp.round */\
        bool p0 = (k == 0) | (k == 4);      /* 0 / 180 deg  */                   \
        bool p1 = (k == 1);                 /* 45           */                   \
        bool p2 = (k == 2);                 /* 90           */                   \
        /* a: p0->CTR  p1->DNR  p2->DNC  else->DNL  (FSEL chain) */              \
        float a_dn = p1 ? (DNR) : (p2 ? (DNC) : (DNL));                          \
        float a    = p0 ? (CTR) : a_dn;                                          \
        /* b: p0->CTL  p1->UPL  p2->UPC  else->UPR */                            \
        float b_up = p1 ? (UPL) : (p2 ? (UPC) : (UPR));                          \
        float b    = p0 ? (CTL) : b_up;                                          \
        o[i] = ((CTC) >= fmaxf(a, b)) ? (CTC) : 0.f;                             \
    }

    NMS_PX(0, ul,   u4.x, u4.y,  lft,  c4.x, c4.y,  dl,   d4.x, d4.y, t4.x)
    NMS_PX(1, u4.x, u4.y, u4.z,  c4.x, c4.y, c4.z,  d4.x, d4.y, d4.z, t4.y)
    NMS_PX(2, u4.y, u4.z, u4.w,  c4.y, c4.z, c4.w,  d4.y, d4.z, d4.w, t4.z)
    NMS_PX(3, u4.z, u4.w, ur,    c4.z, c4.w, rgt,   d4.z, d4.w, dr,   t4.w)

    #undef NMS_PX

    // left / right image borders
    if (w0 == 0)       o[0] = 0.f;
    if (w0 == WW - 4)  o[3] = 0.f;

    *reinterpret_cast<float4*>(out + base) = make_float4(o[0], o[1], o[2], o[3]);
}

extern "C" void kernel_launch(void* const* d_in, const int* in_sizes, int n_in,
                              void* d_out, int out_size)
{
    const float* img   = (const float*)d_in[0];
    const float* theta = (const float*)d_in[1];
    float*       out   = (float*)d_out;

    const int n_quads = HH * (WW / 4);     // 4,194,304 threads
    const int block   = 256;
    const int grid    = n_quads / block;   // 16384
    nms_kernel<<<grid, block>>>(img, theta, out);
}

// round 9
// speedup vs baseline: 1.6919x; 1.0662x over previous
#include <cuda_runtime.h>

#define HH 4096
#define WW 4096
#define NPIX (HH * WW)

// 2D tiles (64 quads x 4 rows per block) for L2 locality + streaming hints for
// theta/out + fully branchless per-pixel body (FSEL chains, no BSSY/BSYNC).

__global__ void __launch_bounds__(256, 7) nms_kernel(
    const float* __restrict__ img,
    const float* __restrict__ theta,
    float* __restrict__ out)
{
    unsigned tid = threadIdx.x;
    unsigned bx  = blockIdx.x & 15u;    // 16 tiles across (64 quads each)
    unsigned by  = blockIdx.x >> 4;     // 1024 tiles down (4 rows each)
    unsigned tx  = tid & 63u;
    unsigned ty  = tid >> 6;

    unsigned h    = (by << 2) + ty;
    unsigned w0   = ((bx << 6) + tx) << 2;
    unsigned base = (h << 12) + w0;

    if (h == 0 || h == HH - 1) {
        __stcs(reinterpret_cast<float4*>(out + base), make_float4(0.f, 0.f, 0.f, 0.f));
        return;
    }

    const float* pc = img + base;

    // ---- 10 independent loads, front-batched (MLP=10) ----
    const float4 t4 = __ldcs(reinterpret_cast<const float4*>(theta + base)); // read-once, evict-first
    const float4 c4 = __ldg(reinterpret_cast<const float4*>(pc));
    const float4 u4 = __ldg(reinterpret_cast<const float4*>(pc - WW));
    const float4 d4 = __ldg(reinterpret_cast<const float4*>(pc + WW));

    // corner clamps only bind for border-zeroed outputs; values never used.
    int uli = (int)base - WW - 1; if (uli < 0) uli = 0;
    int dri = (int)base + WW + 4; if (dri >= NPIX) dri = NPIX - 1;

    const float lft = __ldg(pc - 1);
    const float rgt = __ldg(pc + 4);
    const float ul  = __ldg(img + uli);
    const float ur  = __ldg(pc - WW + 4);
    const float dl  = __ldg(pc + WW - 1);
    const float dr  = __ldg(img + dri);

    const float RCP45 = 1.0f / 45.0f;   // RN(1/45)
    float o[4];

    // column layout (j = image column w0-1+j):
    // up:  ul  u4.x u4.y u4.z u4.w ur
    // ct:  lft c4.x c4.y c4.z c4.w rgt
    // dn:  dl  d4.x d4.y d4.z d4.w dr
    #define NMS_PX(i, UPL, UPC, UPR, CTL, CTC, CTR, DNL, DNC, DNR, TH)          \
    {                                                                            \
        float deg = __fmul_rn((TH), 57.29577951308232f);                         \
        if (deg < 0.f) deg = __fadd_rn(deg, 180.f);                              \
        float q0 = __fmul_rn(deg, RCP45);                                        \
        float rr = __fmaf_rn(-45.f, q0, deg);                                    \
        float qf = __fmaf_rn(rr, RCP45, q0);                                     \
        int   k  = __float2int_rn(qf);      /* F2I.RNI = half-even = jnp.round */\
        bool p0 = (k == 0) | (k == 4);      /* 0 / 180 deg  */                   \
        bool p1 = (k == 1);                 /* 45           */                   \
        bool p2 = (k == 2);                 /* 90           */                   \
        float a_dn = p1 ? (DNR) : (p2 ? (DNC) : (DNL));                          \
        float a    = p0 ? (CTR) : a_dn;                                          \
        float b_up = p1 ? (UPL) : (p2 ? (UPC) : (UPR));                          \
        float b    = p0 ? (CTL) : b_up;                                          \
        o[i] = ((CTC) >= fmaxf(a, b)) ? (CTC) : 0.f;                             \
    }

    NMS_PX(0, ul,   u4.x, u4.y,  lft,  c4.x, c4.y,  dl,   d4.x, d4.y, t4.x)
    NMS_PX(1, u4.x, u4.y, u4.z,  c4.x, c4.y, c4.z,  d4.x, d4.y, d4.z, t4.y)
    NMS_PX(2, u4.y, u4.z, u4.w,  c4.y, c4.z, c4.w,  d4.y, d4.z, d4.w, t4.z)
    NMS_PX(3, u4.z, u4.w, ur,    c4.z, c4.w, rgt,   d4.z, d4.w, dr,   t4.w)

    #undef NMS_PX

    // left / right image borders
    if (w0 == 0)       o[0] = 0.f;
    if (w0 == WW - 4)  o[3] = 0.f;

    __stcs(reinterpret_cast<float4*>(out + base),
           make_float4(o[0], o[1], o[2], o[3]));     // never re-read: stream it
}

extern "C" void kernel_launch(void* const* d_in, const int* in_sizes, int n_in,
                              void* d_out, int out_size)
{
    const float* img   = (const float*)d_in[0];
    const float* theta = (const float*)d_in[1];
    float*       out   = (float*)d_out;

    const int grid = 16 * 1024;   // 16 tiles-x * 1024 tiles-y
    nms_kernel<<<grid, 256>>>(img, theta, out);
}